// round 2
// baseline (speedup 1.0000x reference)
#include <cuda_runtime.h>
#include <cuda_bf16.h>

// ---------------- problem constants ----------------
#define Bb   2
#define Ss   2048
#define Dd   1024
#define Hh   16
#define HD   64
#define NB   16          // S / 128 blocks
#define ROWS 4096        // B*S
#define NQKV 3072        // 3*D

#define NEG_INF (__int_as_float(0xff800000))

// ---------------- device scratch (no allocs allowed) ----------------
__device__ float g_qkv[ROWS * NQKV];   // [4096][3072]: cols 0..1023 Q, 1024..2047 K, 2048..3071 V (head-major, hd=64)
__device__ float g_att[ROWS * Dd];     // attention output [4096][1024]
__device__ int   g_mask[NB * NB];      // canonical block mask (1 = masked/skip)

// ---------------- helpers ----------------
__device__ __forceinline__ unsigned int f2tf(float f) {
    unsigned int u;
    asm("cvt.rna.tf32.f32 %0, %1;" : "=r"(u) : "f"(f));   // round-to-nearest: unbiased (raw truncation is NOT)
    return u;
}

__device__ __forceinline__ void mma8(float* c, const unsigned int* a, const unsigned int* b) {
    asm volatile(
        "mma.sync.aligned.m16n8k8.row.col.f32.tf32.tf32.f32 "
        "{%0,%1,%2,%3}, {%4,%5,%6,%7}, {%8,%9}, {%0,%1,%2,%3};"
        : "+f"(c[0]), "+f"(c[1]), "+f"(c[2]), "+f"(c[3])
        : "r"(a[0]), "r"(a[1]), "r"(a[2]), "r"(a[3]), "r"(b[0]), "r"(b[1]));
}

// ---------------- mask canonicalization ----------------
// block_mask is jax bool; wire dtype ambiguous. Classify from the first 256 bytes
// (always in-bounds for every hypothesis), then expand to int g_mask[256].
__global__ void mask_canon_kernel(const unsigned char* raw) {
    if (threadIdx.x != 0) return;
    const unsigned int* w = (const unsigned int*)raw;
    bool all01 = true, allf = true;
    for (int i = 0; i < 64; i++) {             // 256 bytes
        unsigned int v = w[i];
        if (v != 0u && v != 1u) all01 = false;
        if (v != 0u && v != 0x3F800000u) allf = false;
    }
    if (all01) {                                // int32 0/1
        for (int i = 0; i < 256; i++) g_mask[i] = (int)w[i];
    } else if (allf) {                          // float32 0.0/1.0
        for (int i = 0; i < 256; i++) g_mask[i] = (w[i] != 0u) ? 1 : 0;
    } else {                                    // uint8 bool (most likely)
        for (int i = 0; i < 256; i++) g_mask[i] = raw[i] ? 1 : 0;
    }
}

// ---------------- TF32 GEMM: C[M,N] = A[M,K] @ B[K,N] (+bias) ----------------
// Block 128x128x32, 8 warps, warp tile 64x32 (4 m16 x 4 n8), reg-prefetch double buffer.
// Smem strides: As 36 (== 4 mod 32 -> A-frag LDS banks = 4g+t, conflict-free),
//               Bs 136 (== 8 mod 32 -> B-frag LDS banks = 8t+g, conflict-free).
#define GBM 128
#define GBN 128
#define GBK 32
#define AS_STR 36
#define BS_STR 136

__global__ __launch_bounds__(256, 1)
void gemm_tf32(const float* __restrict__ A, const float* __restrict__ Bm,
               const float* __restrict__ bias, float* __restrict__ C,
               int M, int N, int K)
{
    __shared__ unsigned int As[GBM * AS_STR];
    __shared__ unsigned int Bs[GBK * BS_STR];

    const int tid  = threadIdx.x;
    const int bm   = blockIdx.y * GBM;
    const int bn   = blockIdx.x * GBN;
    const int lane = tid & 31;
    const int warp = tid >> 5;
    const int g    = lane >> 2;
    const int t    = lane & 3;
    const int wm   = (warp & 1) * 64;
    const int wn   = (warp >> 1) * 32;

    float acc[4][4][4];
    #pragma unroll
    for (int i = 0; i < 4; i++)
        #pragma unroll
        for (int j = 0; j < 4; j++)
            #pragma unroll
            for (int e = 0; e < 4; e++) acc[i][j][e] = 0.0f;

    float4 pa[4], pb[4];

    auto loadA = [&](int k0) {
        #pragma unroll
        for (int j = 0; j < 4; j++) {
            int item = tid + j * 256;            // 1024 float4 = 128 rows x 8
            int row = item >> 3, c4 = item & 7;
            pa[j] = *(const float4*)(A + (size_t)(bm + row) * K + k0 + c4 * 4);
        }
    };
    auto loadB = [&](int k0) {
        #pragma unroll
        for (int j = 0; j < 4; j++) {
            int item = tid + j * 256;            // 1024 float4 = 32 rows x 32
            int row = item >> 5, c4 = item & 31;
            pb[j] = *(const float4*)(Bm + (size_t)(k0 + row) * N + bn + c4 * 4);
        }
    };
    auto storeAB = [&]() {
        #pragma unroll
        for (int j = 0; j < 4; j++) {
            int item = tid + j * 256;
            int row = item >> 3, c4 = (item & 7) * 4;
            unsigned int* p = &As[row * AS_STR + c4];
            p[0] = f2tf(pa[j].x); p[1] = f2tf(pa[j].y);
            p[2] = f2tf(pa[j].z); p[3] = f2tf(pa[j].w);
        }
        #pragma unroll
        for (int j = 0; j < 4; j++) {
            int item = tid + j * 256;
            int row = item >> 5, c4 = (item & 31) * 4;
            unsigned int* p = &Bs[row * BS_STR + c4];
            p[0] = f2tf(pb[j].x); p[1] = f2tf(pb[j].y);
            p[2] = f2tf(pb[j].z); p[3] = f2tf(pb[j].w);
        }
    };

    loadA(0); loadB(0);
    storeAB();
    __syncthreads();

    for (int k0 = GBK; k0 <= K; k0 += GBK) {
        if (k0 < K) { loadA(k0); loadB(k0); }   // prefetch next slab into regs (latency overlapped)

        #pragma unroll
        for (int kk = 0; kk < GBK; kk += 8) {
            unsigned int afr[4][4], bfr[4][2];
            #pragma unroll
            for (int mi = 0; mi < 4; mi++) {
                int rb = wm + mi * 16;
                afr[mi][0] = As[(rb + g    ) * AS_STR + kk + t    ];
                afr[mi][1] = As[(rb + g + 8) * AS_STR + kk + t    ];
                afr[mi][2] = As[(rb + g    ) * AS_STR + kk + t + 4];
                afr[mi][3] = As[(rb + g + 8) * AS_STR + kk + t + 4];
            }
            #pragma unroll
            for (int ni = 0; ni < 4; ni++) {
                int cb = wn + ni * 8;
                bfr[ni][0] = Bs[(kk + t    ) * BS_STR + cb + g];
                bfr[ni][1] = Bs[(kk + t + 4) * BS_STR + cb + g];
            }
            #pragma unroll
            for (int mi = 0; mi < 4; mi++)
                #pragma unroll
                for (int ni = 0; ni < 4; ni++)
                    mma8(acc[mi][ni], afr[mi], bfr[ni]);
        }
        __syncthreads();
        if (k0 < K) { storeAB(); __syncthreads(); }
    }

    // epilogue: c0:(r,2t) c1:(r,2t+1) c2:(r+8,2t) c3:(r+8,2t+1)
    #pragma unroll
    for (int mi = 0; mi < 4; mi++) {
        #pragma unroll
        for (int ni = 0; ni < 4; ni++) {
            int r0 = bm + wm + mi * 16 + g;
            int c0 = bn + wn + ni * 8 + 2 * t;
            float bx = 0.f, by = 0.f;
            if (bias) { bx = bias[c0]; by = bias[c0 + 1]; }
            C[(size_t)(r0    ) * N + c0    ] = acc[mi][ni][0] + bx;
            C[(size_t)(r0    ) * N + c0 + 1] = acc[mi][ni][1] + by;
            C[(size_t)(r0 + 8) * N + c0    ] = acc[mi][ni][2] + bx;
            C[(size_t)(r0 + 8) * N + c0 + 1] = acc[mi][ni][3] + by;
        }
    }
}

// ---------------- block-sparse flash attention ----------------
// One CTA per (q-block 128, head, batch). 8 warps, each owns 16 q-rows x all 128 keys.
// Q fragments in registers. K smem stride 68 (banks 4g+t), V stride 72 (banks 8t+g),
// P restaged via smem stride 132 (banks 4g+t) because tf32 C-frag != A-frag layout.
#define KSTR 68
#define VSTR 72
#define PSTR 132
#define ATT_SMEM ((128 * VSTR + 128 * PSTR) * 4)   // 104448 bytes

__global__ __launch_bounds__(256, 1)
void attn_kernel()
{
    extern __shared__ unsigned int sm[];
    unsigned int* KV = sm;                 // 128*72  (K uses stride 68 within same buffer)
    unsigned int* P  = sm + 128 * VSTR;    // 128*132

    const int qi = blockIdx.x, h = blockIdx.y, b = blockIdx.z;
    const int tid  = threadIdx.x;
    const int lane = tid & 31;
    const int warp = tid >> 5;
    const int g    = lane >> 2;
    const int t    = lane & 3;

    const float scale = 0.125f;            // hd^-0.5 = 1/8, exact

    // Q fragments (A-operand layout), scaled then rounded to tf32
    unsigned int qa[8][4];
    {
        int r0 = b * Ss + qi * 128 + warp * 16 + g;
        const float* q0 = g_qkv + (size_t)r0 * NQKV + h * HD;
        const float* q1 = q0 + (size_t)8 * NQKV;
        #pragma unroll
        for (int kk = 0; kk < 8; kk++) {
            qa[kk][0] = f2tf(q0[kk * 8 + t    ] * scale);
            qa[kk][1] = f2tf(q1[kk * 8 + t    ] * scale);
            qa[kk][2] = f2tf(q0[kk * 8 + t + 4] * scale);
            qa[kk][3] = f2tf(q1[kk * 8 + t + 4] * scale);
        }
    }

    float m0 = NEG_INF, m1 = NEG_INF, l0 = 0.f, l1 = 0.f;
    float o[8][4];
    #pragma unroll
    for (int i = 0; i < 8; i++)
        #pragma unroll
        for (int e = 0; e < 4; e++) o[i][e] = 0.f;

    const float* Kbase = g_qkv + (size_t)b * Ss * NQKV + Dd + h * HD;        // K columns
    const float* Vbase = Kbase + Dd;                                          // V columns

    for (int kb = 0; kb < NB; kb++) {
        if (g_mask[qi * NB + kb]) continue;   // fully -inf block: contributes nothing

        // ---- load K block [128 keys][64] -> KV (stride 68), tf32 ----
        {
            const float* src = Kbase + (size_t)kb * 128 * NQKV;
            #pragma unroll
            for (int j = 0; j < 8; j++) {
                int item = tid + j * 256;             // 2048 float4
                int key = item >> 4, d4 = (item & 15) * 4;
                float4 v = *(const float4*)(src + (size_t)key * NQKV + d4);
                unsigned int* p = &KV[key * KSTR + d4];
                p[0] = f2tf(v.x); p[1] = f2tf(v.y); p[2] = f2tf(v.z); p[3] = f2tf(v.w);
            }
        }
        __syncthreads();

        // ---- S = (Q*scale) @ K^T : warp computes 16x128 ----
        float sc[16][4];
        #pragma unroll
        for (int ni = 0; ni < 16; ni++)
            #pragma unroll
            for (int e = 0; e < 4; e++) sc[ni][e] = 0.f;

        #pragma unroll
        for (int kk = 0; kk < 8; kk++) {
            #pragma unroll
            for (int ni = 0; ni < 16; ni++) {
                unsigned int bb[2];
                bb[0] = KV[(ni * 8 + g) * KSTR + kk * 8 + t    ];
                bb[1] = KV[(ni * 8 + g) * KSTR + kk * 8 + t + 4];
                mma8(sc[ni], qa[kk], bb);
            }
        }

        // ---- online softmax (rows g and g+8; stats shared by the 4 lanes of each quad) ----
        float mx0 = NEG_INF, mx1 = NEG_INF;
        #pragma unroll
        for (int ni = 0; ni < 16; ni++) {
            mx0 = fmaxf(mx0, fmaxf(sc[ni][0], sc[ni][1]));
            mx1 = fmaxf(mx1, fmaxf(sc[ni][2], sc[ni][3]));
        }
        mx0 = fmaxf(mx0, __shfl_xor_sync(0xffffffffu, mx0, 1));
        mx0 = fmaxf(mx0, __shfl_xor_sync(0xffffffffu, mx0, 2));
        mx1 = fmaxf(mx1, __shfl_xor_sync(0xffffffffu, mx1, 1));
        mx1 = fmaxf(mx1, __shfl_xor_sync(0xffffffffu, mx1, 2));

        float nm0 = fmaxf(m0, mx0), nm1 = fmaxf(m1, mx1);
        float a0 = __expf(m0 - nm0), a1 = __expf(m1 - nm1);   // exp(-inf)=0 on first block
        m0 = nm0; m1 = nm1;

        float s0 = 0.f, s1 = 0.f;
        #pragma unroll
        for (int ni = 0; ni < 16; ni++) {
            sc[ni][0] = __expf(sc[ni][0] - nm0);
            sc[ni][1] = __expf(sc[ni][1] - nm0);
            sc[ni][2] = __expf(sc[ni][2] - nm1);
            sc[ni][3] = __expf(sc[ni][3] - nm1);
            s0 += sc[ni][0] + sc[ni][1];
            s1 += sc[ni][2] + sc[ni][3];
        }
        s0 += __shfl_xor_sync(0xffffffffu, s0, 1);
        s0 += __shfl_xor_sync(0xffffffffu, s0, 2);
        s1 += __shfl_xor_sync(0xffffffffu, s1, 1);
        s1 += __shfl_xor_sync(0xffffffffu, s1, 2);
        l0 = l0 * a0 + s0;
        l1 = l1 * a1 + s1;

        #pragma unroll
        for (int ni = 0; ni < 8; ni++) {
            o[ni][0] *= a0; o[ni][1] *= a0;
            o[ni][2] *= a1; o[ni][3] *= a1;
        }

        // ---- stage P to smem (tf32, A-operand source layout) ----
        {
            int pr0 = warp * 16 + g, pr1 = pr0 + 8;
            #pragma unroll
            for (int ni = 0; ni < 16; ni++) {
                int col = ni * 8 + 2 * t;
                P[pr0 * PSTR + col    ] = f2tf(sc[ni][0]);
                P[pr0 * PSTR + col + 1] = f2tf(sc[ni][1]);
                P[pr1 * PSTR + col    ] = f2tf(sc[ni][2]);
                P[pr1 * PSTR + col + 1] = f2tf(sc[ni][3]);
            }
        }
        __syncthreads();   // K fully consumed, P fully written

        // ---- load V block [128 keys][64] -> KV (stride 72), tf32 ----
        {
            const float* src = Vbase + (size_t)kb * 128 * NQKV;
            #pragma unroll
            for (int j = 0; j < 8; j++) {
                int item = tid + j * 256;
                int key = item >> 4, d4 = (item & 15) * 4;
                float4 v = *(const float4*)(src + (size_t)key * NQKV + d4);
                unsigned int* p = &KV[key * VSTR + d4];
                p[0] = f2tf(v.x); p[1] = f2tf(v.y); p[2] = f2tf(v.z); p[3] = f2tf(v.w);
            }
        }
        __syncthreads();

        // ---- O += P @ V : k over 128 keys (16 k-steps), 8 n8 tiles over hd=64 ----
        {
            int rb = warp * 16;
            #pragma unroll
            for (int kk = 0; kk < 16; kk++) {
                unsigned int pf[4];
                pf[0] = P[(rb + g    ) * PSTR + kk * 8 + t    ];
                pf[1] = P[(rb + g + 8) * PSTR + kk * 8 + t    ];
                pf[2] = P[(rb + g    ) * PSTR + kk * 8 + t + 4];
                pf[3] = P[(rb + g + 8) * PSTR + kk * 8 + t + 4];
                #pragma unroll
                for (int ni = 0; ni < 8; ni++) {
                    unsigned int bb[2];
                    bb[0] = KV[(kk * 8 + t    ) * VSTR + ni * 8 + g];
                    bb[1] = KV[(kk * 8 + t + 4) * VSTR + ni * 8 + g];
                    mma8(o[ni], pf, bb);
                }
            }
        }
        __syncthreads();   // KV/P about to be overwritten next iteration
    }

    // ---- epilogue: normalize by l and write [b, qrow, h*64+d] ----
    float inv0 = 1.0f / l0, inv1 = 1.0f / l1;
    int r0 = qi * 128 + warp * 16 + g;
    float* dst0 = g_att + (size_t)(b * Ss + r0) * Dd + h * HD;
    float* dst1 = dst0 + (size_t)8 * Dd;
    #pragma unroll
    for (int ni = 0; ni < 8; ni++) {
        int col = ni * 8 + 2 * t;
        dst0[col    ] = o[ni][0] * inv0;
        dst0[col + 1] = o[ni][1] * inv0;
        dst1[col    ] = o[ni][2] * inv1;
        dst1[col + 1] = o[ni][3] * inv1;
    }
}

// ---------------- launch ----------------
extern "C" void kernel_launch(void* const* d_in, const int* in_sizes, int n_in,
                              void* d_out, int out_size)
{
    const float*         x      = (const float*)d_in[0];
    const float*         w_qkv  = (const float*)d_in[1];
    const float*         w_proj = (const float*)d_in[2];
    const float*         b_proj = (const float*)d_in[3];
    const unsigned char* bmask  = (const unsigned char*)d_in[4];
    float*               out    = (float*)d_out;

    (void)in_sizes; (void)n_in; (void)out_size;

    // immediate (non-stream) APIs: capture-safe, idempotent
    cudaFuncSetAttribute(attn_kernel, cudaFuncAttributeMaxDynamicSharedMemorySize, ATT_SMEM);
    void* p_qkv = nullptr; cudaGetSymbolAddress(&p_qkv, g_qkv);
    void* p_att = nullptr; cudaGetSymbolAddress(&p_att, g_att);

    mask_canon_kernel<<<1, 32>>>(bmask);

    // QKV: [4096,1024] @ [1024,3072]
    gemm_tf32<<<dim3(NQKV / GBN, ROWS / GBM), 256>>>(x, w_qkv, nullptr, (float*)p_qkv,
                                                     ROWS, NQKV, Dd);

    // attention: grid (q-blocks, heads, batch)
    attn_kernel<<<dim3(NB, Hh, Bb), 256, ATT_SMEM>>>();

    // proj: [4096,1024] @ [1024,1024] + bias
    gemm_tf32<<<dim3(Dd / GBN, ROWS / GBM), 256>>>((float*)p_att, w_proj, b_proj, out,
                                                   ROWS, Dd, Dd);
}

// round 3
// speedup vs baseline: 1.1166x; 1.1166x over previous
#include <cuda_runtime.h>
#include <cuda_bf16.h>

// ---------------- problem constants ----------------
#define Bb   2
#define Ss   2048
#define Dd   1024
#define Hh   16
#define HD   64
#define NB   16
#define ROWS 4096        // B*S
#define NQKV 3072        // 3*D

#define NEG_INF (__int_as_float(0xff800000))

// ---------------- device scratch (tf32 bit patterns stored as uint) ----------------
__device__ unsigned int g_x    [ROWS * Dd];     // x, tf32 bits
__device__ unsigned int g_wqkv [Dd * NQKV];     // w_qkv, tf32 bits
__device__ unsigned int g_wproj[Dd * Dd];       // w_proj, tf32 bits
__device__ unsigned int g_qkv  [ROWS * NQKV];   // QKV output, tf32 bits (Q pre-scaled by 0.125)
__device__ unsigned int g_att  [ROWS * Dd];     // attention output, tf32 bits
__device__ int          g_mask [NB * NB];

// ---------------- helpers ----------------
__device__ __forceinline__ unsigned int f2tf(float f) {
    unsigned int u;
    asm("cvt.rna.tf32.f32 %0, %1;" : "=r"(u) : "f"(f));
    return u;
}

__device__ __forceinline__ void mma8(float* c, const unsigned int* a, const unsigned int* b) {
    asm volatile(
        "mma.sync.aligned.m16n8k8.row.col.f32.tf32.tf32.f32 "
        "{%0,%1,%2,%3}, {%4,%5,%6,%7}, {%8,%9}, {%0,%1,%2,%3};"
        : "+f"(c[0]), "+f"(c[1]), "+f"(c[2]), "+f"(c[3])
        : "r"(a[0]), "r"(a[1]), "r"(a[2]), "r"(a[3]), "r"(b[0]), "r"(b[1]));
}

__device__ __forceinline__ unsigned int s2u(const void* p) {
    return (unsigned int)__cvta_generic_to_shared(p);
}
__device__ __forceinline__ void cpa16(unsigned int s, const void* g) {
    asm volatile("cp.async.cg.shared.global [%0], [%1], 16;" :: "r"(s), "l"(g));
}
#define CP_COMMIT() asm volatile("cp.async.commit_group;")
template<int N> __device__ __forceinline__ void cp_wait() {
    asm volatile("cp.async.wait_group %0;" :: "n"(N));
}

// ---------------- mask canonicalization ----------------
__global__ void mask_canon_kernel(const unsigned char* raw) {
    if (threadIdx.x != 0) return;
    const unsigned int* w = (const unsigned int*)raw;
    bool all01 = true, allf = true;
    for (int i = 0; i < 64; i++) {
        unsigned int v = w[i];
        if (v != 0u && v != 1u) all01 = false;
        if (v != 0u && v != 0x3F800000u) allf = false;
    }
    if (all01) {
        for (int i = 0; i < 256; i++) g_mask[i] = (int)w[i];
    } else if (allf) {
        for (int i = 0; i < 256; i++) g_mask[i] = (w[i] != 0u) ? 1 : 0;
    } else {
        for (int i = 0; i < 256; i++) g_mask[i] = raw[i] ? 1 : 0;
    }
}

// ---------------- fp32 -> tf32-bits conversion (grid-stride, vectorized) ----------------
__global__ void convert_tf32(const float* __restrict__ src, unsigned int* __restrict__ dst, int n4) {
    for (int i = blockIdx.x * blockDim.x + threadIdx.x; i < n4; i += gridDim.x * blockDim.x) {
        float4 v = ((const float4*)src)[i];
        uint4 o;
        o.x = f2tf(v.x); o.y = f2tf(v.y); o.z = f2tf(v.z); o.w = f2tf(v.w);
        ((uint4*)dst)[i] = o;
    }
}

// ---------------- TF32 GEMM, operands pre-converted, cp.async 2-stage ----------------
// Block 128x128x32, 8 warps, warp tile 64x32. Strides 36 / 136 (conflict-free frag LDS).
// mode 0: C float = acc + bias (proj).  mode 1: C uint = f2tf(acc * (col<Dd ? 0.125 : 1)) (QKV).
#define GBM 128
#define GBN 128
#define GBK 32
#define AS_STR 36
#define BS_STR 136
#define STAGE_W (GBM * AS_STR + GBK * BS_STR)       // 8960 words
#define GEMM_SMEM (2 * STAGE_W * 4)                 // 71680 bytes

__global__ __launch_bounds__(256, 2)
void gemm_pre(const unsigned int* __restrict__ A, const unsigned int* __restrict__ B,
              const float* __restrict__ bias, void* __restrict__ Cout,
              int M, int N, int K, int mode)
{
    extern __shared__ unsigned int sm[];

    const int tid  = threadIdx.x;
    const int lane = tid & 31;
    const int warp = tid >> 5;
    const int g    = lane >> 2;
    const int t    = lane & 3;
    const int bm   = blockIdx.y * GBM;
    const int bn   = blockIdx.x * GBN;
    const int wm   = (warp & 1) * 64;
    const int wn   = (warp >> 1) * 32;

    float acc[4][4][4];
    #pragma unroll
    for (int i = 0; i < 4; i++)
        #pragma unroll
        for (int j = 0; j < 4; j++)
            #pragma unroll
            for (int e = 0; e < 4; e++) acc[i][j][e] = 0.0f;

    auto issue = [&](int k0, int s) {
        unsigned int* Asb = sm + s * STAGE_W;
        unsigned int* Bsb = Asb + GBM * AS_STR;
        #pragma unroll
        for (int j = 0; j < 4; j++) {                 // A: 128 rows x 8 chunks
            int item = tid + j * 256;
            int r = item >> 3, c = item & 7;
            cpa16(s2u(Asb + r * AS_STR + c * 4), A + (size_t)(bm + r) * K + k0 + c * 4);
        }
        #pragma unroll
        for (int j = 0; j < 4; j++) {                 // B: 32 rows x 32 chunks
            int item = tid + j * 256;
            int r = item >> 5, c = item & 31;
            cpa16(s2u(Bsb + r * BS_STR + c * 4), B + (size_t)(k0 + r) * N + bn + c * 4);
        }
        CP_COMMIT();
    };

    issue(0, 0);
    int s = 0;
    for (int k0 = 0; k0 < K; k0 += GBK) {
        bool nx = (k0 + GBK < K);
        if (nx) { issue(k0 + GBK, s ^ 1); cp_wait<1>(); }
        else    { cp_wait<0>(); }
        __syncthreads();

        const unsigned int* Asb = sm + s * STAGE_W;
        const unsigned int* Bsb = Asb + GBM * AS_STR;

        #pragma unroll
        for (int kk = 0; kk < GBK; kk += 8) {
            unsigned int afr[4][4], bfr[4][2];
            #pragma unroll
            for (int mi = 0; mi < 4; mi++) {
                int rb = wm + mi * 16;
                afr[mi][0] = Asb[(rb + g    ) * AS_STR + kk + t    ];
                afr[mi][1] = Asb[(rb + g + 8) * AS_STR + kk + t    ];
                afr[mi][2] = Asb[(rb + g    ) * AS_STR + kk + t + 4];
                afr[mi][3] = Asb[(rb + g + 8) * AS_STR + kk + t + 4];
            }
            #pragma unroll
            for (int ni = 0; ni < 4; ni++) {
                int cb = wn + ni * 8;
                bfr[ni][0] = Bsb[(kk + t    ) * BS_STR + cb + g];
                bfr[ni][1] = Bsb[(kk + t + 4) * BS_STR + cb + g];
            }
            #pragma unroll
            for (int mi = 0; mi < 4; mi++)
                #pragma unroll
                for (int ni = 0; ni < 4; ni++)
                    mma8(acc[mi][ni], afr[mi], bfr[ni]);
        }
        __syncthreads();
        s ^= 1;
    }

    // epilogue: c0:(r,2t) c1:(r,2t+1) c2:(r+8,2t) c3:(r+8,2t+1)
    if (mode == 0) {
        float* C = (float*)Cout;
        #pragma unroll
        for (int mi = 0; mi < 4; mi++) {
            #pragma unroll
            for (int ni = 0; ni < 4; ni++) {
                int r0 = bm + wm + mi * 16 + g;
                int c0 = bn + wn + ni * 8 + 2 * t;
                float bx = bias ? bias[c0] : 0.f;
                float by = bias ? bias[c0 + 1] : 0.f;
                C[(size_t)(r0    ) * N + c0    ] = acc[mi][ni][0] + bx;
                C[(size_t)(r0    ) * N + c0 + 1] = acc[mi][ni][1] + by;
                C[(size_t)(r0 + 8) * N + c0    ] = acc[mi][ni][2] + bx;
                C[(size_t)(r0 + 8) * N + c0 + 1] = acc[mi][ni][3] + by;
            }
        }
    } else {
        unsigned int* C = (unsigned int*)Cout;
        #pragma unroll
        for (int mi = 0; mi < 4; mi++) {
            #pragma unroll
            for (int ni = 0; ni < 4; ni++) {
                int r0 = bm + wm + mi * 16 + g;
                int c0 = bn + wn + ni * 8 + 2 * t;
                float sc = (c0 < Dd) ? 0.125f : 1.0f;   // Q columns pre-scaled (exact pow2)
                C[(size_t)(r0    ) * N + c0    ] = f2tf(acc[mi][ni][0] * sc);
                C[(size_t)(r0    ) * N + c0 + 1] = f2tf(acc[mi][ni][1] * sc);
                C[(size_t)(r0 + 8) * N + c0    ] = f2tf(acc[mi][ni][2] * sc);
                C[(size_t)(r0 + 8) * N + c0 + 1] = f2tf(acc[mi][ni][3] * sc);
            }
        }
    }
}

// ---------------- block-sparse flash attention (cp.async pipelined) ----------------
// K double-buffered (stride 68), V single (stride 72), P staging (stride 132).
// Per live block: wait K -> S-mma -> issue next K -> softmax -> P store -> wait V -> P@V -> issue next V.
#define KSTR 68
#define VSTR 72
#define PSTR 132
#define KBUF_W (128 * KSTR)
#define VBUF_W (128 * VSTR)
#define PBUF_W (128 * PSTR)
#define ATT_SMEM ((2 * KBUF_W + VBUF_W + PBUF_W) * 4)   // 174080 bytes

__global__ __launch_bounds__(256, 1)
void attn_kernel()
{
    extern __shared__ unsigned int sm[];
    unsigned int* kbuf0 = sm;
    unsigned int* kbuf1 = sm + KBUF_W;
    unsigned int* vb    = sm + 2 * KBUF_W;
    unsigned int* P     = sm + 2 * KBUF_W + VBUF_W;
    __shared__ int live[NB + 1];

    const int qi = blockIdx.x, h = blockIdx.y, b = blockIdx.z;
    const int tid  = threadIdx.x;
    const int lane = tid & 31;
    const int warp = tid >> 5;
    const int g    = lane >> 2;
    const int t    = lane & 3;

    if (tid == 0) {
        int n = 0;
        for (int kb = 0; kb < NB; kb++)
            if (!g_mask[qi * NB + kb]) live[n++] = kb;
        live[NB] = n;
    }
    __syncthreads();
    const int nlive = live[NB];                        // >= 1 (diagonal/lower never masked)

    const unsigned int* Kbase = g_qkv + (size_t)b * Ss * NQKV + Dd + h * HD;
    const unsigned int* Vbase = Kbase + Dd;

    auto issueK = [&](int kb, unsigned int* dst) {
        const unsigned int* src = Kbase + (size_t)kb * 128 * NQKV;
        #pragma unroll
        for (int j = 0; j < 8; j++) {                  // 128 keys x 16 chunks
            int item = tid + j * 256;
            int key = item >> 4, c = item & 15;
            cpa16(s2u(dst + key * KSTR + c * 4), src + (size_t)key * NQKV + c * 4);
        }
        CP_COMMIT();
    };
    auto issueV = [&](int kb) {
        const unsigned int* src = Vbase + (size_t)kb * 128 * NQKV;
        #pragma unroll
        for (int j = 0; j < 8; j++) {
            int item = tid + j * 256;
            int key = item >> 4, c = item & 15;
            cpa16(s2u(vb + key * VSTR + c * 4), src + (size_t)key * NQKV + c * 4);
        }
        CP_COMMIT();
    };

    issueK(live[0], kbuf0);
    issueV(live[0]);

    // Q fragments: already tf32 bits, pre-scaled by 0.125 in the QKV epilogue
    unsigned int qa[8][4];
    {
        int r0 = b * Ss + qi * 128 + warp * 16 + g;
        const unsigned int* q0 = g_qkv + (size_t)r0 * NQKV + h * HD;
        const unsigned int* q1 = q0 + (size_t)8 * NQKV;
        #pragma unroll
        for (int kk = 0; kk < 8; kk++) {
            qa[kk][0] = q0[kk * 8 + t    ];
            qa[kk][1] = q1[kk * 8 + t    ];
            qa[kk][2] = q0[kk * 8 + t + 4];
            qa[kk][3] = q1[kk * 8 + t + 4];
        }
    }

    float m0 = NEG_INF, m1 = NEG_INF, l0 = 0.f, l1 = 0.f;
    float o[8][4];
    #pragma unroll
    for (int i = 0; i < 8; i++)
        #pragma unroll
        for (int e = 0; e < 4; e++) o[i][e] = 0.f;

    for (int i = 0; i < nlive; i++) {
        const unsigned int* kcur = (i & 1) ? kbuf1 : kbuf0;
        unsigned int*       kalt = (i & 1) ? kbuf0 : kbuf1;
        const bool nx = (i + 1 < nlive);

        // pending at loop head: {K_i, V_i}; complete K_i
        cp_wait<1>();
        __syncthreads();

        // ---- S = Q @ K^T ----
        float sc[16][4];
        #pragma unroll
        for (int ni = 0; ni < 16; ni++)
            #pragma unroll
            for (int e = 0; e < 4; e++) sc[ni][e] = 0.f;

        #pragma unroll
        for (int kk = 0; kk < 8; kk++) {
            #pragma unroll
            for (int ni = 0; ni < 16; ni++) {
                unsigned int bb[2];
                bb[0] = kcur[(ni * 8 + g) * KSTR + kk * 8 + t    ];
                bb[1] = kcur[(ni * 8 + g) * KSTR + kk * 8 + t + 4];
                mma8(sc[ni], qa[kk], bb);
            }
        }

        // prefetch next K into the alternate buffer (its last reader synced an iteration ago)
        if (nx) issueK(live[i + 1], kalt);

        // ---- online softmax ----
        float mx0 = NEG_INF, mx1 = NEG_INF;
        #pragma unroll
        for (int ni = 0; ni < 16; ni++) {
            mx0 = fmaxf(mx0, fmaxf(sc[ni][0], sc[ni][1]));
            mx1 = fmaxf(mx1, fmaxf(sc[ni][2], sc[ni][3]));
        }
        mx0 = fmaxf(mx0, __shfl_xor_sync(0xffffffffu, mx0, 1));
        mx0 = fmaxf(mx0, __shfl_xor_sync(0xffffffffu, mx0, 2));
        mx1 = fmaxf(mx1, __shfl_xor_sync(0xffffffffu, mx1, 1));
        mx1 = fmaxf(mx1, __shfl_xor_sync(0xffffffffu, mx1, 2));

        float nm0 = fmaxf(m0, mx0), nm1 = fmaxf(m1, mx1);
        float a0 = __expf(m0 - nm0), a1 = __expf(m1 - nm1);
        m0 = nm0; m1 = nm1;

        float s0 = 0.f, s1 = 0.f;
        #pragma unroll
        for (int ni = 0; ni < 16; ni++) {
            sc[ni][0] = __expf(sc[ni][0] - nm0);
            sc[ni][1] = __expf(sc[ni][1] - nm0);
            sc[ni][2] = __expf(sc[ni][2] - nm1);
            sc[ni][3] = __expf(sc[ni][3] - nm1);
            s0 += sc[ni][0] + sc[ni][1];
            s1 += sc[ni][2] + sc[ni][3];
        }
        s0 += __shfl_xor_sync(0xffffffffu, s0, 1);
        s0 += __shfl_xor_sync(0xffffffffu, s0, 2);
        s1 += __shfl_xor_sync(0xffffffffu, s1, 1);
        s1 += __shfl_xor_sync(0xffffffffu, s1, 2);
        l0 = l0 * a0 + s0;
        l1 = l1 * a1 + s1;

        #pragma unroll
        for (int ni = 0; ni < 8; ni++) {
            o[ni][0] *= a0; o[ni][1] *= a0;
            o[ni][2] *= a1; o[ni][3] *= a1;
        }

        // ---- stage P (tf32 bits) ----
        {
            int pr0 = warp * 16 + g, pr1 = pr0 + 8;
            #pragma unroll
            for (int ni = 0; ni < 16; ni++) {
                int col = ni * 8 + 2 * t;
                P[pr0 * PSTR + col    ] = f2tf(sc[ni][0]);
                P[pr0 * PSTR + col + 1] = f2tf(sc[ni][1]);
                P[pr1 * PSTR + col    ] = f2tf(sc[ni][2]);
                P[pr1 * PSTR + col + 1] = f2tf(sc[ni][3]);
            }
        }
        __syncthreads();                    // P fully written

        // complete V_i (pending: {V_i} or {V_i, K_{i+1}})
        if (nx) cp_wait<1>(); else cp_wait<0>();
        __syncthreads();

        // ---- O += P @ V ----
        {
            int rb = warp * 16;
            #pragma unroll
            for (int kk = 0; kk < 16; kk++) {
                unsigned int pf[4];
                pf[0] = P[(rb + g    ) * PSTR + kk * 8 + t    ];
                pf[1] = P[(rb + g + 8) * PSTR + kk * 8 + t    ];
                pf[2] = P[(rb + g    ) * PSTR + kk * 8 + t + 4];
                pf[3] = P[(rb + g + 8) * PSTR + kk * 8 + t + 4];
                #pragma unroll
                for (int ni = 0; ni < 8; ni++) {
                    unsigned int bb[2];
                    bb[0] = vb[(kk * 8 + t    ) * VSTR + ni * 8 + g];
                    bb[1] = vb[(kk * 8 + t + 4) * VSTR + ni * 8 + g];
                    mma8(o[ni], pf, bb);
                }
            }
        }
        __syncthreads();                    // all warps done with vb and P

        if (nx) issueV(live[i + 1]);        // refill the single V buffer
    }

    // ---- epilogue: normalize and store tf32 bits for the proj GEMM ----
    float inv0 = 1.0f / l0, inv1 = 1.0f / l1;
    int r0 = qi * 128 + warp * 16 + g;
    unsigned int* dst0 = g_att + (size_t)(b * Ss + r0) * Dd + h * HD;
    unsigned int* dst1 = dst0 + (size_t)8 * Dd;
    #pragma unroll
    for (int ni = 0; ni < 8; ni++) {
        int col = ni * 8 + 2 * t;
        dst0[col    ] = f2tf(o[ni][0] * inv0);
        dst0[col + 1] = f2tf(o[ni][1] * inv0);
        dst1[col    ] = f2tf(o[ni][2] * inv1);
        dst1[col + 1] = f2tf(o[ni][3] * inv1);
    }
}

// ---------------- launch ----------------
extern "C" void kernel_launch(void* const* d_in, const int* in_sizes, int n_in,
                              void* d_out, int out_size)
{
    const float*         x      = (const float*)d_in[0];
    const float*         w_qkv  = (const float*)d_in[1];
    const float*         w_proj = (const float*)d_in[2];
    const float*         b_proj = (const float*)d_in[3];
    const unsigned char* bmask  = (const unsigned char*)d_in[4];
    float*               out    = (float*)d_out;

    (void)in_sizes; (void)n_in; (void)out_size;

    cudaFuncSetAttribute(gemm_pre,    cudaFuncAttributeMaxDynamicSharedMemorySize, GEMM_SMEM);
    cudaFuncSetAttribute(attn_kernel, cudaFuncAttributeMaxDynamicSharedMemorySize, ATT_SMEM);

    void *p_x, *p_wqkv, *p_wproj, *p_qkv, *p_att;
    cudaGetSymbolAddress(&p_x,     g_x);
    cudaGetSymbolAddress(&p_wqkv,  g_wqkv);
    cudaGetSymbolAddress(&p_wproj, g_wproj);
    cudaGetSymbolAddress(&p_qkv,   g_qkv);
    cudaGetSymbolAddress(&p_att,   g_att);

    mask_canon_kernel<<<1, 32>>>(bmask);

    convert_tf32<<<1184, 256>>>(x,      (unsigned int*)p_x,     ROWS * Dd  / 4);
    convert_tf32<<<1184, 256>>>(w_qkv,  (unsigned int*)p_wqkv,  Dd * NQKV  / 4);
    convert_tf32<<<1184, 256>>>(w_proj, (unsigned int*)p_wproj, Dd * Dd    / 4);

    // QKV: [4096,1024] @ [1024,3072] -> tf32 bits (Q scaled by 0.125)
    gemm_pre<<<dim3(NQKV / GBN, ROWS / GBM), 256, GEMM_SMEM>>>(
        (const unsigned int*)p_x, (const unsigned int*)p_wqkv, nullptr, p_qkv,
        ROWS, NQKV, Dd, 1);

    attn_kernel<<<dim3(NB, Hh, Bb), 256, ATT_SMEM>>>();

    // proj: [4096,1024] @ [1024,1024] + bias -> float out
    gemm_pre<<<dim3(Dd / GBN, ROWS / GBM), 256, GEMM_SMEM>>>(
        (const unsigned int*)p_att, (const unsigned int*)p_wproj, b_proj, out,
        ROWS, Dd, Dd, 0);
}

// round 4
// speedup vs baseline: 1.1226x; 1.0054x over previous
#include <cuda_runtime.h>
#include <cuda_bf16.h>

// ---------------- problem constants ----------------
#define Bb   2
#define Ss   2048
#define Dd   1024
#define Hh   16
#define HD   64
#define NB   16
#define ROWS 4096        // B*S
#define NQKV 3072        // 3*D

#define NEG_INF (__int_as_float(0xff800000))

// ---------------- device scratch (tf32 bit patterns stored as uint) ----------------
__device__ unsigned int g_x    [ROWS * Dd];
__device__ unsigned int g_wqkv [Dd * NQKV];
__device__ unsigned int g_wproj[Dd * Dd];
__device__ unsigned int g_qkv  [ROWS * NQKV];   // QKV out, tf32 bits (Q pre-scaled by 0.125)
__device__ unsigned int g_att  [ROWS * Dd];     // attention out, tf32 bits
__device__ int          g_mask [NB * NB];

// ---------------- helpers ----------------
__device__ __forceinline__ unsigned int f2tf(float f) {
    unsigned int u;
    asm("cvt.rna.tf32.f32 %0, %1;" : "=r"(u) : "f"(f));
    return u;
}

__device__ __forceinline__ void mma8(float* c, const unsigned int* a, const unsigned int* b) {
    asm volatile(
        "mma.sync.aligned.m16n8k8.row.col.f32.tf32.tf32.f32 "
        "{%0,%1,%2,%3}, {%4,%5,%6,%7}, {%8,%9}, {%0,%1,%2,%3};"
        : "+f"(c[0]), "+f"(c[1]), "+f"(c[2]), "+f"(c[3])
        : "r"(a[0]), "r"(a[1]), "r"(a[2]), "r"(a[3]), "r"(b[0]), "r"(b[1]));
}

__device__ __forceinline__ unsigned int s2u(const void* p) {
    return (unsigned int)__cvta_generic_to_shared(p);
}
__device__ __forceinline__ void cpa16(unsigned int s, const void* g) {
    asm volatile("cp.async.cg.shared.global [%0], [%1], 16;" :: "r"(s), "l"(g));
}
#define CP_COMMIT() asm volatile("cp.async.commit_group;")
template<int N> __device__ __forceinline__ void cp_wait() {
    asm volatile("cp.async.wait_group %0;" :: "n"(N));
}

// ---------------- mask canonicalization ----------------
__global__ void mask_canon_kernel(const unsigned char* raw) {
    if (threadIdx.x != 0) return;
    const unsigned int* w = (const unsigned int*)raw;
    bool all01 = true, allf = true;
    for (int i = 0; i < 64; i++) {
        unsigned int v = w[i];
        if (v != 0u && v != 1u) all01 = false;
        if (v != 0u && v != 0x3F800000u) allf = false;
    }
    if (all01) {
        for (int i = 0; i < 256; i++) g_mask[i] = (int)w[i];
    } else if (allf) {
        for (int i = 0; i < 256; i++) g_mask[i] = (w[i] != 0u) ? 1 : 0;
    } else {
        for (int i = 0; i < 256; i++) g_mask[i] = raw[i] ? 1 : 0;
    }
}

// ---------------- fused fp32 -> tf32 conversion of x, w_qkv, w_proj ----------------
#define N4_X  (ROWS * Dd  / 4)
#define N4_WQ (Dd * NQKV  / 4)
#define N4_WP (Dd * Dd    / 4)
__global__ void convert_all(const float* __restrict__ x, const float* __restrict__ wq,
                            const float* __restrict__ wp) {
    const int total = N4_X + N4_WQ + N4_WP;
    for (int i = blockIdx.x * blockDim.x + threadIdx.x; i < total; i += gridDim.x * blockDim.x) {
        const float4* src; uint4* dst; int j;
        if (i < N4_X)              { src = (const float4*)x;  dst = (uint4*)g_x;     j = i; }
        else if (i < N4_X + N4_WQ) { src = (const float4*)wq; dst = (uint4*)g_wqkv;  j = i - N4_X; }
        else                       { src = (const float4*)wp; dst = (uint4*)g_wproj; j = i - N4_X - N4_WQ; }
        float4 v = src[j];
        uint4 o;
        o.x = f2tf(v.x); o.y = f2tf(v.y); o.z = f2tf(v.z); o.w = f2tf(v.w);
        dst[j] = o;
    }
}

// ---------------- TF32 GEMM, 3-stage cp.async ring, ONE sync per k-slab ----------------
// Block 128x128x32, 8 warps, warp tile 64x32. Strides 36 / 136 (conflict-free frag LDS).
// mode 0: C float = acc + bias (proj).  mode 1: C uint = f2tf(acc * (col<Dd ? 0.125 : 1)) (QKV).
#define GBM 128
#define GBN 128
#define GBK 32
#define AS_STR 36
#define BS_STR 136
#define STAGE_W (GBM * AS_STR + GBK * BS_STR)       // 8960 words = 35840 B
#define NSTAGE 3
#define GEMM_SMEM (NSTAGE * STAGE_W * 4)            // 107520 B

__global__ __launch_bounds__(256, 2)
void gemm_pre(const unsigned int* __restrict__ A, const unsigned int* __restrict__ B,
              const float* __restrict__ bias, void* __restrict__ Cout,
              int M, int N, int K, int mode)
{
    extern __shared__ unsigned int sm[];

    const int tid  = threadIdx.x;
    const int lane = tid & 31;
    const int warp = tid >> 5;
    const int g    = lane >> 2;
    const int t    = lane & 3;
    const int bm   = blockIdx.y * GBM;
    const int bn   = blockIdx.x * GBN;
    const int wm   = (warp & 1) * 64;
    const int wn   = (warp >> 1) * 32;

    float acc[4][4][4];
    #pragma unroll
    for (int i = 0; i < 4; i++)
        #pragma unroll
        for (int j = 0; j < 4; j++)
            #pragma unroll
            for (int e = 0; e < 4; e++) acc[i][j][e] = 0.0f;

    auto issue = [&](int k0, int s) {
        unsigned int* Asb = sm + s * STAGE_W;
        unsigned int* Bsb = Asb + GBM * AS_STR;
        #pragma unroll
        for (int j = 0; j < 4; j++) {                 // A: 128 rows x 8 chunks
            int item = tid + j * 256;
            int r = item >> 3, c = item & 7;
            cpa16(s2u(Asb + r * AS_STR + c * 4), A + (size_t)(bm + r) * K + k0 + c * 4);
        }
        #pragma unroll
        for (int j = 0; j < 4; j++) {                 // B: 32 rows x 32 chunks
            int item = tid + j * 256;
            int r = item >> 5, c = item & 31;
            cpa16(s2u(Bsb + r * BS_STR + c * 4), B + (size_t)(k0 + r) * N + bn + c * 4);
        }
        CP_COMMIT();
    };

    issue(0, 0);
    issue(GBK, 1);

    const int niter = K / GBK;
    int s = 0;
    for (int it = 0; it < niter; it++) {
        if (it == niter - 1) cp_wait<0>(); else cp_wait<1>();
        __syncthreads();                       // the ONLY barrier per slab:
                                               // also proves all warps finished slab it-1,
                                               // so re-issuing into stage (s+2)%3 is safe.
        if (it + 2 < niter) issue((it + 2) * GBK, (s + 2) % NSTAGE);

        const unsigned int* Asb = sm + s * STAGE_W;
        const unsigned int* Bsb = Asb + GBM * AS_STR;

        #pragma unroll
        for (int kk = 0; kk < GBK; kk += 8) {
            unsigned int afr[4][4], bfr[4][2];
            #pragma unroll
            for (int mi = 0; mi < 4; mi++) {
                int rb = wm + mi * 16;
                afr[mi][0] = Asb[(rb + g    ) * AS_STR + kk + t    ];
                afr[mi][1] = Asb[(rb + g + 8) * AS_STR + kk + t    ];
                afr[mi][2] = Asb[(rb + g    ) * AS_STR + kk + t + 4];
                afr[mi][3] = Asb[(rb + g + 8) * AS_STR + kk + t + 4];
            }
            #pragma unroll
            for (int ni = 0; ni < 4; ni++) {
                int cb = wn + ni * 8;
                bfr[ni][0] = Bsb[(kk + t    ) * BS_STR + cb + g];
                bfr[ni][1] = Bsb[(kk + t + 4) * BS_STR + cb + g];
            }
            #pragma unroll
            for (int mi = 0; mi < 4; mi++)
                #pragma unroll
                for (int ni = 0; ni < 4; ni++)
                    mma8(acc[mi][ni], afr[mi], bfr[ni]);
        }
        s = (s + 1) % NSTAGE;
    }

    // epilogue: c0:(r,2t) c1:(r,2t+1) c2:(r+8,2t) c3:(r+8,2t+1)
    if (mode == 0) {
        float* C = (float*)Cout;
        #pragma unroll
        for (int mi = 0; mi < 4; mi++) {
            #pragma unroll
            for (int ni = 0; ni < 4; ni++) {
                int r0 = bm + wm + mi * 16 + g;
                int c0 = bn + wn + ni * 8 + 2 * t;
                float bx = bias ? bias[c0] : 0.f;
                float by = bias ? bias[c0 + 1] : 0.f;
                C[(size_t)(r0    ) * N + c0    ] = acc[mi][ni][0] + bx;
                C[(size_t)(r0    ) * N + c0 + 1] = acc[mi][ni][1] + by;
                C[(size_t)(r0 + 8) * N + c0    ] = acc[mi][ni][2] + bx;
                C[(size_t)(r0 + 8) * N + c0 + 1] = acc[mi][ni][3] + by;
            }
        }
    } else {
        unsigned int* C = (unsigned int*)Cout;
        #pragma unroll
        for (int mi = 0; mi < 4; mi++) {
            #pragma unroll
            for (int ni = 0; ni < 4; ni++) {
                int r0 = bm + wm + mi * 16 + g;
                int c0 = bn + wn + ni * 8 + 2 * t;
                float sc = (c0 < Dd) ? 0.125f : 1.0f;
                C[(size_t)(r0    ) * N + c0    ] = f2tf(acc[mi][ni][0] * sc);
                C[(size_t)(r0    ) * N + c0 + 1] = f2tf(acc[mi][ni][1] * sc);
                C[(size_t)(r0 + 8) * N + c0    ] = f2tf(acc[mi][ni][2] * sc);
                C[(size_t)(r0 + 8) * N + c0 + 1] = f2tf(acc[mi][ni][3] * sc);
            }
        }
    }
}

// ---------------- block-sparse flash attention ----------------
// K and V both double-buffered; P staging ELIMINATED (C-frag -> A-frag is an
// intra-quad permutation: element (g, kk*8+c) lives in quad-lane c>>1, reg c&1,
// so pf is built with 8 shfl + 4 selects per kk). 2 barriers per live block.
#define KSTR 68
#define VSTR 72
#define KBUF_W (128 * KSTR)
#define VBUF_W (128 * VSTR)
#define ATT_SMEM ((2 * KBUF_W + 2 * VBUF_W) * 4)   // 143360 B

__global__ __launch_bounds__(256, 1)
void attn_kernel()
{
    extern __shared__ unsigned int sm[];
    unsigned int* kb0 = sm;
    unsigned int* kb1 = sm + KBUF_W;
    unsigned int* vb0 = sm + 2 * KBUF_W;
    unsigned int* vb1 = sm + 2 * KBUF_W + VBUF_W;
    __shared__ int live[NB + 1];

    const int qi = blockIdx.x, h = blockIdx.y, b = blockIdx.z;
    const int tid  = threadIdx.x;
    const int lane = tid & 31;
    const int warp = tid >> 5;
    const int g    = lane >> 2;
    const int t    = lane & 3;

    if (tid == 0) {
        int n = 0;
        for (int kb = 0; kb < NB; kb++)
            if (!g_mask[qi * NB + kb]) live[n++] = kb;
        live[NB] = n;
    }
    __syncthreads();
    const int nlive = live[NB];                      // >= 1 (diagonal never masked)

    const unsigned int* Kbase = g_qkv + (size_t)b * Ss * NQKV + Dd + h * HD;
    const unsigned int* Vbase = Kbase + Dd;

    auto issueK = [&](int kb, unsigned int* dst) {
        const unsigned int* src = Kbase + (size_t)kb * 128 * NQKV;
        #pragma unroll
        for (int j = 0; j < 8; j++) {
            int item = tid + j * 256;
            int key = item >> 4, c = item & 15;
            cpa16(s2u(dst + key * KSTR + c * 4), src + (size_t)key * NQKV + c * 4);
        }
        CP_COMMIT();
    };
    auto issueV = [&](int kb, unsigned int* dst) {
        const unsigned int* src = Vbase + (size_t)kb * 128 * NQKV;
        #pragma unroll
        for (int j = 0; j < 8; j++) {
            int item = tid + j * 256;
            int key = item >> 4, c = item & 15;
            cpa16(s2u(dst + key * VSTR + c * 4), src + (size_t)key * NQKV + c * 4);
        }
        CP_COMMIT();
    };

    issueK(live[0], kb0);
    issueV(live[0], vb0);

    // Q fragments: tf32 bits, pre-scaled by 0.125 in the QKV epilogue
    unsigned int qa[8][4];
    {
        int r0 = b * Ss + qi * 128 + warp * 16 + g;
        const unsigned int* q0 = g_qkv + (size_t)r0 * NQKV + h * HD;
        const unsigned int* q1 = q0 + (size_t)8 * NQKV;
        #pragma unroll
        for (int kk = 0; kk < 8; kk++) {
            qa[kk][0] = q0[kk * 8 + t    ];
            qa[kk][1] = q1[kk * 8 + t    ];
            qa[kk][2] = q0[kk * 8 + t + 4];
            qa[kk][3] = q1[kk * 8 + t + 4];
        }
    }

    float m0 = NEG_INF, m1 = NEG_INF, l0 = 0.f, l1 = 0.f;
    float o[8][4];
    #pragma unroll
    for (int i = 0; i < 8; i++)
        #pragma unroll
        for (int e = 0; e < 4; e++) o[i][e] = 0.f;

    const int qbase = lane & ~3;                     // quad base lane
    const int src0  = qbase + (t >> 1);              // holder of col t   (and t mod 2)
    const int src1  = src0 + 2;                      // holder of col t+4

    for (int i = 0; i < nlive; i++) {
        const unsigned int* kcur = (i & 1) ? kb1 : kb0;
        unsigned int*       kalt = (i & 1) ? kb0 : kb1;
        const unsigned int* vcur = (i & 1) ? vb1 : vb0;
        unsigned int*       valt = (i & 1) ? vb0 : vb1;
        const bool nx = (i + 1 < nlive);

        // pending: {K(i), V(i)} -> complete K(i)
        cp_wait<1>();
        __syncthreads();            // barrier #1: K ready; all warps done with iter i-1

        // ---- S = Q @ K^T ----
        float sc[16][4];
        #pragma unroll
        for (int ni = 0; ni < 16; ni++)
            #pragma unroll
            for (int e = 0; e < 4; e++) sc[ni][e] = 0.f;

        #pragma unroll
        for (int kk = 0; kk < 8; kk++) {
            #pragma unroll
            for (int ni = 0; ni < 16; ni++) {
                unsigned int bb[2];
                bb[0] = kcur[(ni * 8 + g) * KSTR + kk * 8 + t    ];
                bb[1] = kcur[(ni * 8 + g) * KSTR + kk * 8 + t + 4];
                mma8(sc[ni], qa[kk], bb);
            }
        }

        if (nx) issueK(live[i + 1], kalt);   // safe: kalt's last reader finished before barrier #1

        // ---- online softmax ----
        float mx0 = NEG_INF, mx1 = NEG_INF;
        #pragma unroll
        for (int ni = 0; ni < 16; ni++) {
            mx0 = fmaxf(mx0, fmaxf(sc[ni][0], sc[ni][1]));
            mx1 = fmaxf(mx1, fmaxf(sc[ni][2], sc[ni][3]));
        }
        mx0 = fmaxf(mx0, __shfl_xor_sync(0xffffffffu, mx0, 1));
        mx0 = fmaxf(mx0, __shfl_xor_sync(0xffffffffu, mx0, 2));
        mx1 = fmaxf(mx1, __shfl_xor_sync(0xffffffffu, mx1, 1));
        mx1 = fmaxf(mx1, __shfl_xor_sync(0xffffffffu, mx1, 2));

        float nm0 = fmaxf(m0, mx0), nm1 = fmaxf(m1, mx1);
        float a0 = __expf(m0 - nm0), a1 = __expf(m1 - nm1);
        m0 = nm0; m1 = nm1;

        float s0 = 0.f, s1 = 0.f;
        #pragma unroll
        for (int ni = 0; ni < 16; ni++) {
            sc[ni][0] = __expf(sc[ni][0] - nm0);
            sc[ni][1] = __expf(sc[ni][1] - nm0);
            sc[ni][2] = __expf(sc[ni][2] - nm1);
            sc[ni][3] = __expf(sc[ni][3] - nm1);
            s0 += sc[ni][0] + sc[ni][1];
            s1 += sc[ni][2] + sc[ni][3];
        }
        s0 += __shfl_xor_sync(0xffffffffu, s0, 1);
        s0 += __shfl_xor_sync(0xffffffffu, s0, 2);
        s1 += __shfl_xor_sync(0xffffffffu, s1, 1);
        s1 += __shfl_xor_sync(0xffffffffu, s1, 2);
        l0 = l0 * a0 + s0;
        l1 = l1 * a1 + s1;

        #pragma unroll
        for (int ni = 0; ni < 8; ni++) {
            o[ni][0] *= a0; o[ni][1] *= a0;
            o[ni][2] *= a1; o[ni][3] *= a1;
        }

        // complete V(i): pending {V(i)} or {V(i), K(i+1)}
        if (nx) cp_wait<1>(); else cp_wait<0>();
        __syncthreads();            // barrier #2: V ready for every warp

        // ---- O += P @ V, P fragments built in-register via quad shuffles ----
        #pragma unroll
        for (int kk = 0; kk < 16; kk++) {
            unsigned int p0 = f2tf(sc[kk][0]), p1 = f2tf(sc[kk][1]);
            unsigned int p2 = f2tf(sc[kk][2]), p3 = f2tf(sc[kk][3]);
            unsigned int e00 = __shfl_sync(0xffffffffu, p0, src0);
            unsigned int e01 = __shfl_sync(0xffffffffu, p1, src0);
            unsigned int e10 = __shfl_sync(0xffffffffu, p2, src0);
            unsigned int e11 = __shfl_sync(0xffffffffu, p3, src0);
            unsigned int f00 = __shfl_sync(0xffffffffu, p0, src1);
            unsigned int f01 = __shfl_sync(0xffffffffu, p1, src1);
            unsigned int f10 = __shfl_sync(0xffffffffu, p2, src1);
            unsigned int f11 = __shfl_sync(0xffffffffu, p3, src1);
            unsigned int pf[4];
            pf[0] = (t & 1) ? e01 : e00;   // (row g,   col kk*8+t)
            pf[1] = (t & 1) ? e11 : e10;   // (row g+8, col kk*8+t)
            pf[2] = (t & 1) ? f01 : f00;   // (row g,   col kk*8+t+4)
            pf[3] = (t & 1) ? f11 : f10;   // (row g+8, col kk*8+t+4)
            #pragma unroll
            for (int ni = 0; ni < 8; ni++) {
                unsigned int bb[2];
                bb[0] = vcur[(kk * 8 + t    ) * VSTR + ni * 8 + g];
                bb[1] = vcur[(kk * 8 + t + 4) * VSTR + ni * 8 + g];
                mma8(o[ni], pf, bb);
            }
        }

        if (nx) issueV(live[i + 1], valt);  // safe: valt's last reader finished before barrier #2
    }

    // ---- epilogue: normalize and store tf32 bits for the proj GEMM ----
    float inv0 = 1.0f / l0, inv1 = 1.0f / l1;
    int r0 = qi * 128 + warp * 16 + g;
    unsigned int* dst0 = g_att + (size_t)(b * Ss + r0) * Dd + h * HD;
    unsigned int* dst1 = dst0 + (size_t)8 * Dd;
    #pragma unroll
    for (int ni = 0; ni < 8; ni++) {
        int col = ni * 8 + 2 * t;
        dst0[col    ] = f2tf(o[ni][0] * inv0);
        dst0[col + 1] = f2tf(o[ni][1] * inv0);
        dst1[col    ] = f2tf(o[ni][2] * inv1);
        dst1[col + 1] = f2tf(o[ni][3] * inv1);
    }
}

// ---------------- launch ----------------
extern "C" void kernel_launch(void* const* d_in, const int* in_sizes, int n_in,
                              void* d_out, int out_size)
{
    const float*         x      = (const float*)d_in[0];
    const float*         w_qkv  = (const float*)d_in[1];
    const float*         w_proj = (const float*)d_in[2];
    const float*         b_proj = (const float*)d_in[3];
    const unsigned char* bmask  = (const unsigned char*)d_in[4];
    float*               out    = (float*)d_out;

    (void)in_sizes; (void)n_in; (void)out_size;

    cudaFuncSetAttribute(gemm_pre,    cudaFuncAttributeMaxDynamicSharedMemorySize, GEMM_SMEM);
    cudaFuncSetAttribute(attn_kernel, cudaFuncAttributeMaxDynamicSharedMemorySize, ATT_SMEM);

    void *p_x, *p_wqkv, *p_wproj, *p_qkv, *p_att;
    cudaGetSymbolAddress(&p_x,     g_x);
    cudaGetSymbolAddress(&p_wqkv,  g_wqkv);
    cudaGetSymbolAddress(&p_wproj, g_wproj);
    cudaGetSymbolAddress(&p_qkv,   g_qkv);
    cudaGetSymbolAddress(&p_att,   g_att);

    mask_canon_kernel<<<1, 32>>>(bmask);
    convert_all<<<1184, 256>>>(x, w_qkv, w_proj);

    // QKV: [4096,1024] @ [1024,3072] -> tf32 bits (Q scaled by 0.125)
    gemm_pre<<<dim3(NQKV / GBN, ROWS / GBM), 256, GEMM_SMEM>>>(
        (const unsigned int*)p_x, (const unsigned int*)p_wqkv, nullptr, p_qkv,
        ROWS, NQKV, Dd, 1);

    attn_kernel<<<dim3(NB, Hh, Bb), 256, ATT_SMEM>>>();

    // proj: [4096,1024] @ [1024,1024] + bias -> float out
    gemm_pre<<<dim3(Dd / GBN, ROWS / GBM), 256, GEMM_SMEM>>>(
        (const unsigned int*)p_att, (const unsigned int*)p_wproj, b_proj, out,
        ROWS, Dd, Dd, 0);
}

// round 6
// speedup vs baseline: 1.9133x; 1.7044x over previous
#include <cuda_runtime.h>
#include <cuda_fp16.h>

// ---------------- problem constants ----------------
#define Bb   2
#define Ss   2048
#define Dd   1024
#define Hh   16
#define HD   64
#define NB   16
#define ROWS 4096        // B*S
#define NQKV 3072        // 3*D

#define NEG_INF (__int_as_float(0xff800000))

// ---------------- device scratch (fp16) ----------------
__device__ __half g_x     [ROWS * Dd];     // x, [4096][1024] K-contig
__device__ __half g_wqkvT [NQKV * Dd];     // w_qkv^T, [3072][1024] K-contig (n-major)
__device__ __half g_wprojT[Dd * Dd];       // w_proj^T, [1024][1024] K-contig
__device__ __half g_qkv   [ROWS * NQKV];   // QKV out (Q pre-scaled by 0.125)
__device__ __half g_att   [ROWS * Dd];     // attention out
__device__ int    g_mask  [NB * NB];

// ---------------- helpers ----------------
__device__ __forceinline__ unsigned int pack2(float a, float b) {
    __half2 h = __floats2half2_rn(a, b);       // low = a (even col), high = b
    return *(unsigned int*)&h;
}
__device__ __forceinline__ void mma16(float* c, const unsigned int* a, const unsigned int* b) {
    asm volatile(
        "mma.sync.aligned.m16n8k16.row.col.f32.f16.f16.f32 "
        "{%0,%1,%2,%3}, {%4,%5,%6,%7}, {%8,%9}, {%0,%1,%2,%3};"
        : "+f"(c[0]), "+f"(c[1]), "+f"(c[2]), "+f"(c[3])
        : "r"(a[0]), "r"(a[1]), "r"(a[2]), "r"(a[3]), "r"(b[0]), "r"(b[1]));
}
__device__ __forceinline__ unsigned int s2u(const void* p) {
    return (unsigned int)__cvta_generic_to_shared(p);
}
__device__ __forceinline__ void cpa16(unsigned int s, const void* g) {
    asm volatile("cp.async.cg.shared.global [%0], [%1], 16;" :: "r"(s), "l"(g));
}
#define CP_COMMIT() asm volatile("cp.async.commit_group;")
template<int N> __device__ __forceinline__ void cp_wait() {
    asm volatile("cp.async.wait_group %0;" :: "n"(N));
}
__device__ __forceinline__ void ldmx4t(unsigned int& r0, unsigned int& r1,
                                       unsigned int& r2, unsigned int& r3, unsigned int addr) {
    asm volatile("ldmatrix.sync.aligned.m8n8.x4.trans.shared.b16 {%0,%1,%2,%3}, [%4];"
                 : "=r"(r0), "=r"(r1), "=r"(r2), "=r"(r3) : "r"(addr));
}

// ---------------- mask canonicalization ----------------
__global__ void mask_canon_kernel(const unsigned char* raw) {
    if (threadIdx.x != 0) return;
    const unsigned int* w = (const unsigned int*)raw;
    bool all01 = true, allf = true;
    for (int i = 0; i < 64; i++) {
        unsigned int v = w[i];
        if (v != 0u && v != 1u) all01 = false;
        if (v != 0u && v != 0x3F800000u) allf = false;
    }
    if (all01)      for (int i = 0; i < 256; i++) g_mask[i] = (int)w[i];
    else if (allf)  for (int i = 0; i < 256; i++) g_mask[i] = (w[i] != 0u) ? 1 : 0;
    else            for (int i = 0; i < 256; i++) g_mask[i] = raw[i] ? 1 : 0;
}

// ---------------- x -> fp16 ----------------
__global__ void convert_x(const float* __restrict__ x) {
    int n4 = ROWS * Dd / 4;
    for (int i = blockIdx.x * blockDim.x + threadIdx.x; i < n4; i += gridDim.x * blockDim.x) {
        float4 v = ((const float4*)x)[i];
        uint2 o;
        o.x = pack2(v.x, v.y);
        o.y = pack2(v.z, v.w);
        ((uint2*)g_x)[i] = o;
    }
}

// ---------------- w [K,N] float -> wT [N,K] fp16 (tiled transpose) ----------------
__global__ void transpose_h(const float* __restrict__ src, __half* __restrict__ dst,
                            int Kk, int Nn) {
    __shared__ float tl[32][33];
    int k0 = blockIdx.y * 32, n0 = blockIdx.x * 32;
    int tx = threadIdx.x, ty = threadIdx.y;      // 32 x 8
    #pragma unroll
    for (int i = 0; i < 32; i += 8)
        tl[ty + i][tx] = src[(size_t)(k0 + ty + i) * Nn + n0 + tx];
    __syncthreads();
    #pragma unroll
    for (int i = 0; i < 32; i += 8)
        dst[(size_t)(n0 + ty + i) * Kk + k0 + tx] = __float2half_rn(tl[tx][ty + i]);
}

// ---------------- fp16 GEMM: C[M,N] = A[M,K] @ BT[N,K]^T ----------------
// Block 128x128x32, 8 warps, warp tile 64x32, 3-stage cp.async ring, 1 barrier/slab.
// smem rows: 16 half2 data + 4 pad = 20 words (str%32==20 -> frag banks conflict-free).
// mode 0: C float = acc + bias.  mode 1: C half = h(acc * (col<Dd ? 0.125 : 1)).
#define GBM 128
#define GBN 128
#define GBK 32
#define RSTR 20
#define TILE_W (128 * RSTR)          // 2560 words
#define STAGE_W (2 * TILE_W)         // 5120 words = 20 KB
#define NSTAGE 3
#define GEMM_SMEM (NSTAGE * STAGE_W * 4)   // 61440 B -> 2 CTAs/SM

__global__ __launch_bounds__(256, 2)
void gemm_f16(const __half* __restrict__ A, const __half* __restrict__ BT,
              const float* __restrict__ bias, void* __restrict__ Cout,
              int M, int N, int K, int mode)
{
    extern __shared__ unsigned int sm[];

    const int tid  = threadIdx.x;
    const int lane = tid & 31;
    const int warp = tid >> 5;
    const int g    = lane >> 2;
    const int t    = lane & 3;
    const int bm   = blockIdx.y * GBM;
    const int bn   = blockIdx.x * GBN;
    const int wm   = (warp & 1) * 64;
    const int wn   = (warp >> 1) * 32;

    float acc[4][4][4];
    #pragma unroll
    for (int i = 0; i < 4; i++)
        #pragma unroll
        for (int j = 0; j < 4; j++)
            #pragma unroll
            for (int e = 0; e < 4; e++) acc[i][j][e] = 0.0f;

    auto issue = [&](int k0, int s) {
        unsigned int* Asb = sm + s * STAGE_W;
        unsigned int* Bsb = Asb + TILE_W;
        #pragma unroll
        for (int q = 0; q < 2; q++) {                 // A: 128 rows x 4 x 16B
            int item = tid + q * 256;
            int r = item >> 2, c = item & 3;
            cpa16(s2u(Asb + r * RSTR + c * 4), A + (size_t)(bm + r) * K + k0 + c * 8);
        }
        #pragma unroll
        for (int q = 0; q < 2; q++) {                 // B: 128 n-rows x 4 x 16B
            int item = tid + q * 256;
            int r = item >> 2, c = item & 3;
            cpa16(s2u(Bsb + r * RSTR + c * 4), BT + (size_t)(bn + r) * K + k0 + c * 8);
        }
        CP_COMMIT();
    };

    issue(0, 0);
    issue(GBK, 1);

    const int niter = K / GBK;
    int s = 0;
    for (int it = 0; it < niter; it++) {
        if (it == niter - 1) cp_wait<0>(); else cp_wait<1>();
        __syncthreads();                              // single barrier per slab
        if (it + 2 < niter) issue((it + 2) * GBK, (s + 2) % NSTAGE);

        const unsigned int* Asb = sm + s * STAGE_W;
        const unsigned int* Bsb = Asb + TILE_W;

        #pragma unroll
        for (int kk = 0; kk < 2; kk++) {              // two k16 steps per 32-slab
            unsigned int afr[4][4], bfr[4][2];
            #pragma unroll
            for (int mi = 0; mi < 4; mi++) {
                int rb = wm + mi * 16;
                afr[mi][0] = Asb[(rb + g    ) * RSTR + kk * 8 + t    ];
                afr[mi][1] = Asb[(rb + g + 8) * RSTR + kk * 8 + t    ];
                afr[mi][2] = Asb[(rb + g    ) * RSTR + kk * 8 + t + 4];
                afr[mi][3] = Asb[(rb + g + 8) * RSTR + kk * 8 + t + 4];
            }
            #pragma unroll
            for (int ni = 0; ni < 4; ni++) {
                int cb = wn + ni * 8;
                bfr[ni][0] = Bsb[(cb + g) * RSTR + kk * 8 + t    ];
                bfr[ni][1] = Bsb[(cb + g) * RSTR + kk * 8 + t + 4];
            }
            #pragma unroll
            for (int mi = 0; mi < 4; mi++)
                #pragma unroll
                for (int ni = 0; ni < 4; ni++)
                    mma16(acc[mi][ni], afr[mi], bfr[ni]);
        }
        s = (s + 1) % NSTAGE;
    }

    // epilogue: c0:(r,2t) c1:(r,2t+1) c2:(r+8,2t) c3:(r+8,2t+1)
    if (mode == 0) {
        float* C = (float*)Cout;
        #pragma unroll
        for (int mi = 0; mi < 4; mi++) {
            #pragma unroll
            for (int ni = 0; ni < 4; ni++) {
                int r0 = bm + wm + mi * 16 + g;
                int c0 = bn + wn + ni * 8 + 2 * t;
                float bx = bias[c0], by = bias[c0 + 1];
                C[(size_t)(r0    ) * N + c0    ] = acc[mi][ni][0] + bx;
                C[(size_t)(r0    ) * N + c0 + 1] = acc[mi][ni][1] + by;
                C[(size_t)(r0 + 8) * N + c0    ] = acc[mi][ni][2] + bx;
                C[(size_t)(r0 + 8) * N + c0 + 1] = acc[mi][ni][3] + by;
            }
        }
    } else {
        __half2* C = (__half2*)Cout;
        #pragma unroll
        for (int mi = 0; mi < 4; mi++) {
            #pragma unroll
            for (int ni = 0; ni < 4; ni++) {
                int r0 = bm + wm + mi * 16 + g;
                int c0 = bn + wn + ni * 8 + 2 * t;
                float sc = (c0 < Dd) ? 0.125f : 1.0f;   // Q pre-scale (exact pow2)
                C[((size_t)(r0    ) * N + c0) >> 1] =
                    __floats2half2_rn(acc[mi][ni][0] * sc, acc[mi][ni][1] * sc);
                C[((size_t)(r0 + 8) * N + c0) >> 1] =
                    __floats2half2_rn(acc[mi][ni][2] * sc, acc[mi][ni][3] * sc);
            }
        }
    }
}

// ---------------- block-sparse flash attention (fp16 MMA) ----------------
// K smem [128 keys][32 half2 + 4 pad] (b-frag banks 4g+t). V smem same stride,
// consumed via ldmatrix.x4.trans (banks 4*key, conflict-free).
// P@V A-fragments come straight from the S C-fragments (pack2) - no shuffles/smem.
#define KSTRW 36
#define KBUF_W (128 * KSTRW)                     // 4608 words
#define ATT_SMEM (4 * KBUF_W * 4)                // 73728 B

__global__ __launch_bounds__(256, 1)
void attn_kernel()
{
    extern __shared__ unsigned int sm[];
    unsigned int* kb0 = sm;
    unsigned int* kb1 = sm + KBUF_W;
    unsigned int* vb0 = sm + 2 * KBUF_W;
    unsigned int* vb1 = sm + 3 * KBUF_W;
    __shared__ int live[NB + 1];

    const int qi = blockIdx.x, h = blockIdx.y, b = blockIdx.z;
    const int tid  = threadIdx.x;
    const int lane = tid & 31;
    const int warp = tid >> 5;
    const int g    = lane >> 2;
    const int t    = lane & 3;

    if (tid == 0) {
        int n = 0;
        for (int kb = 0; kb < NB; kb++)
            if (!g_mask[qi * NB + kb]) live[n++] = kb;
        live[NB] = n;
    }
    __syncthreads();
    const int nlive = live[NB];

    const __half* Kbase = g_qkv + (size_t)b * Ss * NQKV + Dd + h * HD;
    const __half* Vbase = Kbase + Dd;

    auto issueT = [&](const __half* base, int kb, unsigned int* dst) {
        const __half* src = base + (size_t)kb * 128 * NQKV;
        #pragma unroll
        for (int q = 0; q < 4; q++) {                // 128 keys x 8 x 16B
            int item = tid + q * 256;
            int key = item >> 3, c = item & 7;
            cpa16(s2u(dst + key * KSTRW + c * 4), src + (size_t)key * NQKV + c * 8);
        }
        CP_COMMIT();
    };

    issueT(Kbase, live[0], kb0);
    issueT(Vbase, live[0], vb0);

    // Q a-fragments (fp16, pre-scaled by 0.125), 4 k16 steps over hd=64
    unsigned int qa[4][4];
    {
        int r0 = b * Ss + qi * 128 + warp * 16 + g;
        const unsigned int* q0 = (const unsigned int*)(g_qkv + (size_t)r0 * NQKV + h * HD);
        const unsigned int* q1 = (const unsigned int*)(g_qkv + (size_t)(r0 + 8) * NQKV + h * HD);
        #pragma unroll
        for (int kk = 0; kk < 4; kk++) {
            qa[kk][0] = q0[kk * 8 + t    ];
            qa[kk][1] = q1[kk * 8 + t    ];
            qa[kk][2] = q0[kk * 8 + t + 4];
            qa[kk][3] = q1[kk * 8 + t + 4];
        }
    }

    float m0 = NEG_INF, m1 = NEG_INF, l0 = 0.f, l1 = 0.f;
    float o[8][4];
    #pragma unroll
    for (int i = 0; i < 8; i++)
        #pragma unroll
        for (int e = 0; e < 4; e++) o[i][e] = 0.f;

    // ldmatrix per-lane address components (matrix msel = lane>>3)
    const int keyoff = ((lane >> 3) & 1) * 8 + (lane & 7);
    const int coloff = (lane >> 4) * 8;

    for (int i = 0; i < nlive; i++) {
        const unsigned int* kcur = (i & 1) ? kb1 : kb0;
        unsigned int*       kalt = (i & 1) ? kb0 : kb1;
        const unsigned int* vcur = (i & 1) ? vb1 : vb0;
        unsigned int*       valt = (i & 1) ? vb0 : vb1;
        const bool nx = (i + 1 < nlive);

        cp_wait<1>();
        __syncthreads();            // barrier #1: K ready, prior iter fully done

        // ---- S = Q @ K^T : 16 ni x 4 kk ----
        float sc[16][4];
        #pragma unroll
        for (int ni = 0; ni < 16; ni++)
            #pragma unroll
            for (int e = 0; e < 4; e++) sc[ni][e] = 0.f;

        #pragma unroll
        for (int kk = 0; kk < 4; kk++) {
            #pragma unroll
            for (int ni = 0; ni < 16; ni++) {
                unsigned int bb[2];
                bb[0] = kcur[(ni * 8 + g) * KSTRW + kk * 8 + t    ];
                bb[1] = kcur[(ni * 8 + g) * KSTRW + kk * 8 + t + 4];
                mma16(sc[ni], qa[kk], bb);
            }
        }

        if (nx) issueT(Kbase, live[i + 1], kalt);

        // ---- online softmax ----
        float mx0 = NEG_INF, mx1 = NEG_INF;
        #pragma unroll
        for (int ni = 0; ni < 16; ni++) {
            mx0 = fmaxf(mx0, fmaxf(sc[ni][0], sc[ni][1]));
            mx1 = fmaxf(mx1, fmaxf(sc[ni][2], sc[ni][3]));
        }
        mx0 = fmaxf(mx0, __shfl_xor_sync(0xffffffffu, mx0, 1));
        mx0 = fmaxf(mx0, __shfl_xor_sync(0xffffffffu, mx0, 2));
        mx1 = fmaxf(mx1, __shfl_xor_sync(0xffffffffu, mx1, 1));
        mx1 = fmaxf(mx1, __shfl_xor_sync(0xffffffffu, mx1, 2));

        float nm0 = fmaxf(m0, mx0), nm1 = fmaxf(m1, mx1);
        float a0 = __expf(m0 - nm0), a1 = __expf(m1 - nm1);
        m0 = nm0; m1 = nm1;

        float s0 = 0.f, s1 = 0.f;
        #pragma unroll
        for (int ni = 0; ni < 16; ni++) {
            sc[ni][0] = __expf(sc[ni][0] - nm0);
            sc[ni][1] = __expf(sc[ni][1] - nm0);
            sc[ni][2] = __expf(sc[ni][2] - nm1);
            sc[ni][3] = __expf(sc[ni][3] - nm1);
            s0 += sc[ni][0] + sc[ni][1];
            s1 += sc[ni][2] + sc[ni][3];
        }
        s0 += __shfl_xor_sync(0xffffffffu, s0, 1);
        s0 += __shfl_xor_sync(0xffffffffu, s0, 2);
        s1 += __shfl_xor_sync(0xffffffffu, s1, 1);
        s1 += __shfl_xor_sync(0xffffffffu, s1, 2);
        l0 = l0 * a0 + s0;
        l1 = l1 * a1 + s1;

        #pragma unroll
        for (int ni = 0; ni < 8; ni++) {
            o[ni][0] *= a0; o[ni][1] *= a0;
            o[ni][2] *= a1; o[ni][3] *= a1;
        }

        if (nx) cp_wait<1>(); else cp_wait<0>();
        __syncthreads();            // barrier #2: V ready for every warp

        // ---- O += P @ V : 8 k16 steps; A-frag = packed S C-frags, B via ldmatrix.trans ----
        const unsigned int vbytes = s2u(vcur);
        #pragma unroll
        for (int kk = 0; kk < 8; kk++) {
            unsigned int pa[4];
            pa[0] = pack2(sc[2 * kk    ][0], sc[2 * kk    ][1]);
            pa[1] = pack2(sc[2 * kk    ][2], sc[2 * kk    ][3]);
            pa[2] = pack2(sc[2 * kk + 1][0], sc[2 * kk + 1][1]);
            pa[3] = pack2(sc[2 * kk + 1][2], sc[2 * kk + 1][3]);
            #pragma unroll
            for (int cp = 0; cp < 4; cp++) {           // 16 hd-cols per ldmatrix.x4
                unsigned int r0, r1, r2, r3;
                unsigned int addr = vbytes + (unsigned int)((kk * 16 + keyoff) * (KSTRW * 4)
                                                            + (cp * 16 + coloff) * 2);
                ldmx4t(r0, r1, r2, r3, addr);
                unsigned int bb[2];
                bb[0] = r0; bb[1] = r1; mma16(o[cp * 2    ], pa, bb);
                bb[0] = r2; bb[1] = r3; mma16(o[cp * 2 + 1], pa, bb);
            }
        }

        if (nx) issueT(Vbase, live[i + 1], valt);
    }

    // ---- epilogue: normalize, store fp16 for the proj GEMM ----
    float inv0 = 1.0f / l0, inv1 = 1.0f / l1;
    int r0 = qi * 128 + warp * 16 + g;
    __half2* dst0 = (__half2*)(g_att + (size_t)(r0 + b * Ss) * Dd + h * HD);
    __half2* dst1 = (__half2*)(g_att + (size_t)(r0 + 8 + b * Ss) * Dd + h * HD);
    #pragma unroll
    for (int ni = 0; ni < 8; ni++) {
        int cw = (ni * 8 + 2 * t) >> 1;
        dst0[cw] = __floats2half2_rn(o[ni][0] * inv0, o[ni][1] * inv0);
        dst1[cw] = __floats2half2_rn(o[ni][2] * inv1, o[ni][3] * inv1);
    }
}

// ---------------- launch ----------------
extern "C" void kernel_launch(void* const* d_in, const int* in_sizes, int n_in,
                              void* d_out, int out_size)
{
    const float*         x      = (const float*)d_in[0];
    const float*         w_qkv  = (const float*)d_in[1];
    const float*         w_proj = (const float*)d_in[2];
    const float*         b_proj = (const float*)d_in[3];
    const unsigned char* bmask  = (const unsigned char*)d_in[4];
    float*               out    = (float*)d_out;

    (void)in_sizes; (void)n_in; (void)out_size;

    cudaFuncSetAttribute(gemm_f16,    cudaFuncAttributeMaxDynamicSharedMemorySize, GEMM_SMEM);
    cudaFuncSetAttribute(attn_kernel, cudaFuncAttributeMaxDynamicSharedMemorySize, ATT_SMEM);

    void *p_x, *p_wqkvT, *p_wprojT, *p_qkv, *p_att;
    cudaGetSymbolAddress(&p_x,      g_x);
    cudaGetSymbolAddress(&p_wqkvT,  g_wqkvT);
    cudaGetSymbolAddress(&p_wprojT, g_wprojT);
    cudaGetSymbolAddress(&p_qkv,    g_qkv);
    cudaGetSymbolAddress(&p_att,    g_att);

    mask_canon_kernel<<<1, 32>>>(bmask);
    convert_x<<<1184, 256>>>(x);
    transpose_h<<<dim3(NQKV / 32, Dd / 32), dim3(32, 8)>>>(w_qkv,  (__half*)p_wqkvT,  Dd, NQKV);
    transpose_h<<<dim3(Dd / 32,   Dd / 32), dim3(32, 8)>>>(w_proj, (__half*)p_wprojT, Dd, Dd);

    // QKV: [4096,1024] @ [1024,3072] -> fp16 (Q scaled 0.125)
    gemm_f16<<<dim3(NQKV / GBN, ROWS / GBM), 256, GEMM_SMEM>>>(
        (const __half*)p_x, (const __half*)p_wqkvT, nullptr, p_qkv,
        ROWS, NQKV, Dd, 1);

    attn_kernel<<<dim3(NB, Hh, Bb), 256, ATT_SMEM>>>();

    // proj: [4096,1024] @ [1024,1024] + bias -> float out
    gemm_f16<<<dim3(Dd / GBN, ROWS / GBM), 256, GEMM_SMEM>>>(
        (const __half*)p_att, (const __half*)p_wprojT, b_proj, out,
        ROWS, Dd, Dd, 0);
}